// round 1
// baseline (speedup 1.0000x reference)
#include <cuda_runtime.h>
#include <cuda_bf16.h>
#include <math.h>

// Problem constants
// x: (B=4, C=256, H=252, W=252), padded to 256x256; ws=8 -> 32x32 windows/img
// N = 4*32*32 = 4096 windows, L = 64, nh = 8, hd = 32
#define BB 4
#define CC 256
#define HH 252
#define WW 252
#define HP 256
#define WP 256

// Scratch (window-layout q/k/v: [N][nh][hd][L]) and attention output image.
__device__ float g_Q[4096 * 8 * 32 * 64];
__device__ float g_K[4096 * 8 * 32 * 64];
__device__ float g_V[4096 * 8 * 32 * 64];
__device__ float g_ATT[4 * 256 * 256 * 256];   // padded image [B][C][256][256]

// ---------------------------------------------------------------------------
// Pointwise-projection GEMM: out[oc, pixel] = sum_c W[oc,c] * X[c, pixel]
// 64x64 tile per block, K=256 in steps of 16, 256 threads, 4x4 microtile.
// MODE 0: X=x_q,  W=w_q  (256 rows) -> write g_Q (window layout)
// MODE 1: X=x_kv, W=w_kv (512 rows) -> write g_K / g_V (window layout)
// MODE 2: X=g_ATT (padded image),  W=w_proj -> write cropped output + bias
// ---------------------------------------------------------------------------
template <int MODE>
__global__ __launch_bounds__(256)
void proj_kernel(const float* __restrict__ X, const float* __restrict__ Wm,
                 const float* __restrict__ bias, float* __restrict__ Out)
{
    __shared__ float Ws[16][64];
    __shared__ float Xs[16][64];

    const int tid = threadIdx.x;
    const int tx = tid & 15;          // pixel group
    const int ty = tid >> 4;          // oc group
    const int p0  = blockIdx.x * 64;  // pixel tile base (padded domain)
    const int oc0 = blockIdx.y * 64;  // output-channel tile base

    // pixel tile is 64 consecutive w within one (b, h) row
    const int b      = p0 >> 16;
    const int hw_lin = p0 & 65535;    // h*256 + w
    const int h      = hw_lin >> 8;
    const int w_base = hw_lin & 255;

    float acc[4][4] = {};

    const int idx = tid * 4;
    const int w_oc = idx >> 4;        // 0..63
    const int w_kk = idx & 15;        // 0,4,8,12
    const int x_kk = idx >> 6;        // 0..15
    const int x_pp = idx & 63;        // 0..60 step 4

    for (int k0 = 0; k0 < 256; k0 += 16) {
        // --- load W tile (64 oc x 16 k), store transposed Ws[k][oc] ---
        {
            const float4 wv = *reinterpret_cast<const float4*>(
                &Wm[(oc0 + w_oc) * 256 + k0 + w_kk]);
            Ws[w_kk + 0][w_oc] = wv.x;
            Ws[w_kk + 1][w_oc] = wv.y;
            Ws[w_kk + 2][w_oc] = wv.z;
            Ws[w_kk + 3][w_oc] = wv.w;
        }
        // --- load X tile (16 k x 64 pixels) ---
        {
            const int c = k0 + x_kk;
            if (MODE == 2) {
                const float4 v = *reinterpret_cast<const float4*>(
                    g_ATT + ((size_t)(b * 256 + c) << 16) + hw_lin + x_pp);
                Xs[x_kk][x_pp + 0] = v.x;
                Xs[x_kk][x_pp + 1] = v.y;
                Xs[x_kk][x_pp + 2] = v.z;
                Xs[x_kk][x_pp + 3] = v.w;
            } else {
                #pragma unroll
                for (int j = 0; j < 4; j++) {
                    const int w = w_base + x_pp + j;
                    float v = 0.f;
                    if (h < HH && w < WW)
                        v = X[((size_t)(b * 256 + c) * HH + h) * WW + w];
                    Xs[x_kk][x_pp + j] = v;
                }
            }
        }
        __syncthreads();

        #pragma unroll
        for (int kk = 0; kk < 16; kk++) {
            float a[4], bb[4];
            #pragma unroll
            for (int i = 0; i < 4; i++) a[i]  = Ws[kk][ty * 4 + i];
            #pragma unroll
            for (int j = 0; j < 4; j++) bb[j] = Xs[kk][tx * 4 + j];
            #pragma unroll
            for (int i = 0; i < 4; i++)
                #pragma unroll
                for (int j = 0; j < 4; j++)
                    acc[i][j] += a[i] * bb[j];
        }
        __syncthreads();
    }

    // --- write out ---
    #pragma unroll
    for (int i = 0; i < 4; i++) {
        const int oc = oc0 + ty * 4 + i;
        #pragma unroll
        for (int j = 0; j < 4; j++) {
            const int p = p0 + tx * 4 + j;
            const int w = p & 255;
            const float v = acc[i][j];
            if (MODE == 0) {
                const int n = (b * 32 + (h >> 3)) * 32 + (w >> 3);
                const int l = ((h & 7) << 3) | (w & 7);
                g_Q[((((n << 3) + (oc >> 5)) << 5) + (oc & 31)) * 64 + l] = v;
            } else if (MODE == 1) {
                const int n = (b * 32 + (h >> 3)) * 32 + (w >> 3);
                const int l = ((h & 7) << 3) | (w & 7);
                const int cc = oc & 255;
                float* dst = (oc < 256) ? g_K : g_V;
                dst[((((n << 3) + (cc >> 5)) << 5) + (cc & 31)) * 64 + l] = v;
            } else {
                if (h < HH && w < WW)
                    Out[((size_t)(b * 256 + oc) * HH + h) * WW + w] = v + bias[oc];
            }
        }
    }
}

// ---------------------------------------------------------------------------
// Attention: one block per (window, head) = 32768 blocks, 64 threads.
// Q/K/V tiles are contiguous 32x64 slabs (d-major). Thread t owns query row l=t.
// ---------------------------------------------------------------------------
__global__ __launch_bounds__(64)
void attn_kernel()
{
    __shared__ float Qs[2048];   // [d][l]
    __shared__ float Ks[2048];   // [d][m]
    __shared__ float Vs[2048];   // [d][m]

    const int nb = blockIdx.x;                 // n*8 + head
    const size_t base = (size_t)nb * 2048;
    const int tid = threadIdx.x;

    for (int i = tid; i < 2048; i += 64) {
        Qs[i] = g_Q[base + i];
        Ks[i] = g_K[base + i];
        Vs[i] = g_V[base + i];
    }
    __syncthreads();

    const int l = tid;
    float q[32];
    #pragma unroll
    for (int d = 0; d < 32; d++) q[d] = Qs[d * 64 + l];

    const float scale = 0.1767766952966369f;   // 1/sqrt(32)
    float lo[64];
    float mx = -1e30f;
    #pragma unroll
    for (int m = 0; m < 64; m++) {
        float s = 0.f;
        #pragma unroll
        for (int d = 0; d < 32; d++) s += q[d] * Ks[d * 64 + m];
        s *= scale;
        lo[m] = s;
        mx = fmaxf(mx, s);
    }
    float sum = 0.f;
    #pragma unroll
    for (int m = 0; m < 64; m++) {
        const float e = __expf(lo[m] - mx);
        lo[m] = e;
        sum += e;
    }
    const float inv = 1.f / sum;

    const int n = nb >> 3, head = nb & 7;
    const int b  = n >> 10;
    const int hw = (n >> 5) & 31;
    const int ww = n & 31;
    const int h = hw * 8 + (l >> 3);
    const int w = ww * 8 + (l & 7);
    float* outp = g_ATT + ((size_t)(b * 256 + head * 32) << 16) + (h << 8) + w;

    #pragma unroll 1
    for (int d = 0; d < 32; d++) {
        float s = 0.f;
        #pragma unroll
        for (int m = 0; m < 64; m++) s += lo[m] * Vs[d * 64 + m];
        outp[(size_t)d << 16] = s * inv;
    }
}

// ---------------------------------------------------------------------------
extern "C" void kernel_launch(void* const* d_in, const int* in_sizes, int n_in,
                              void* d_out, int out_size)
{
    const float* x_q    = (const float*)d_in[0];
    const float* x_kv   = (const float*)d_in[1];
    const float* w_q    = (const float*)d_in[2];
    const float* w_kv   = (const float*)d_in[3];
    const float* w_proj = (const float*)d_in[4];
    const float* b_proj = (const float*)d_in[5];
    float* out = (float*)d_out;

    const int pixTiles = (BB * HP * WP) / 64;  // 4096

    dim3 blk(256);
    proj_kernel<0><<<dim3(pixTiles, 4), blk>>>(x_q,  w_q,  nullptr, nullptr);
    proj_kernel<1><<<dim3(pixTiles, 8), blk>>>(x_kv, w_kv, nullptr, nullptr);
    attn_kernel<<<32768, 64>>>();
    proj_kernel<2><<<dim3(pixTiles, 4), blk>>>(nullptr, w_proj, b_proj, out);
}

// round 3
// speedup vs baseline: 1.6184x; 1.6184x over previous
#include <cuda_runtime.h>
#include <cuda_bf16.h>
#include <cstdint>
#include <math.h>

// Problem constants
#define BB 4
#define CC 256
#define HH 252
#define WW 252
#define HP 256
#define WP 256

// Scratch: window-layout q/k/v [N=4096][nh=8][hd=32][L=64], attention image.
__device__ float g_Q[4096 * 8 * 32 * 64];
__device__ float g_K[4096 * 8 * 32 * 64];
__device__ float g_V[4096 * 8 * 32 * 64];
__device__ float g_ATT[4 * 256 * 256 * 256];   // padded image [B][C][256][256]

// Pre-split weights (bf16 hi/lo): wq(256x256) | wkv(512x256) | wproj(256x256)
__device__ __nv_bfloat16 g_Whi[262144];
__device__ __nv_bfloat16 g_Wlo[262144];

// ---------------------------------------------------------------------------
__device__ __forceinline__ uint32_t smem_u32(const void* p) {
    uint32_t a;
    asm("{ .reg .u64 t; cvta.to.shared.u64 t, %1; cvt.u32.u64 %0, t; }"
        : "=r"(a) : "l"(p));
    return a;
}
#define LDSM_X4(r0, r1, r2, r3, addr)                                          \
    asm volatile("ldmatrix.sync.aligned.m8n8.x4.shared.b16 {%0,%1,%2,%3}, [%4];" \
                 : "=r"(r0), "=r"(r1), "=r"(r2), "=r"(r3) : "r"(addr))
#define LDSM_X4_T(r0, r1, r2, r3, addr)                                        \
    asm volatile("ldmatrix.sync.aligned.m8n8.x4.trans.shared.b16 {%0,%1,%2,%3}, [%4];" \
                 : "=r"(r0), "=r"(r1), "=r"(r2), "=r"(r3) : "r"(addr))

__device__ __forceinline__ void mma_bf16(float* d, const uint32_t* a,
                                         uint32_t b0, uint32_t b1) {
    asm volatile(
        "mma.sync.aligned.m16n8k16.row.col.f32.bf16.bf16.f32 "
        "{%0,%1,%2,%3}, {%4,%5,%6,%7}, {%8,%9}, {%0,%1,%2,%3};"
        : "+f"(d[0]), "+f"(d[1]), "+f"(d[2]), "+f"(d[3])
        : "r"(a[0]), "r"(a[1]), "r"(a[2]), "r"(a[3]), "r"(b0), "r"(b1));
}

// ---------------------------------------------------------------------------
// Weight prep: fp32 -> (hi, lo) bf16 split.
// ---------------------------------------------------------------------------
__global__ void prep_w(const float* __restrict__ wq, const float* __restrict__ wkv,
                       const float* __restrict__ wproj)
{
    int i = blockIdx.x * 256 + threadIdx.x;          // 0 .. 262143
    float v;
    if (i < 65536)       v = wq[i];
    else if (i < 196608) v = wkv[i - 65536];
    else                 v = wproj[i - 196608];
    __nv_bfloat16 hi = __float2bfloat16(v);
    g_Whi[i] = hi;
    g_Wlo[i] = __float2bfloat16(v - __bfloat162float(hi));
}

// ---------------------------------------------------------------------------
// HMMA projection GEMM. D[oc(128), pixel(128)] = W[oc,c] X[c,pixel], K=256.
// Split-bf16 3-term into fp32 accum. 8 warps: warp_m = wid&3 (32 oc rows),
// warp_n = wid>>2 (64 pixels). K chunks of 32.
// A smem: [128 oc][k 0..31] bf16, pitch 40 elems (80B)  -> ldmatrix rows ok
// B smem: [32 k][128 pix]  bf16, pitch 136 elems (272B) -> ldmatrix.trans ok
// MODE 0: X=x_q  -> g_Q (window scatter)
// MODE 1: X=x_kv -> g_K / g_V
// MODE 2: X=g_ATT -> cropped Out + bias
// ---------------------------------------------------------------------------
template <int MODE>
__global__ __launch_bounds__(256)
void proj_mma(const float* __restrict__ X, int woff,
              const float* __restrict__ bias, float* __restrict__ Out)
{
    __shared__ __nv_bfloat16 sAH[128 * 40];
    __shared__ __nv_bfloat16 sAL[128 * 40];
    __shared__ __nv_bfloat16 sBH[32 * 136];
    __shared__ __nv_bfloat16 sBL[32 * 136];

    const int tid  = threadIdx.x;
    const int wid  = tid >> 5;
    const int lane = tid & 31;
    const int warp_m = wid & 3;
    const int warp_n = wid >> 2;

    const int p0  = blockIdx.x * 128;
    const int oc0 = blockIdx.y * 128;
    const int b   = p0 >> 16;
    const int rem = p0 & 65535;
    const int h   = rem >> 8;
    const int w0  = rem & 255;

    const uint32_t uAH = smem_u32(sAH);
    const uint32_t uAL = smem_u32(sAL);
    const uint32_t uBH = smem_u32(sBH);
    const uint32_t uBL = smem_u32(sBL);

    float acc[2][8][4];
    #pragma unroll
    for (int i = 0; i < 2; i++)
        #pragma unroll
        for (int j = 0; j < 8; j++)
            #pragma unroll
            for (int k = 0; k < 4; k++) acc[i][j][k] = 0.f;

    // ldmatrix lane address components
    const uint32_t aLaneOff = (uint32_t)((warp_m * 32 + (lane & 15)) * 80 + (lane >> 4) * 16);
    const uint32_t bLaneOff = (uint32_t)(((lane & 7) + ((lane >> 3) & 1) * 8) * 272
                                         + (warp_n * 64 + (lane >> 4) * 8) * 2);

    for (int ch = 0; ch < 8; ch++) {
        const int k0 = ch * 32;
        // ---- A tile: 128 oc x 32 k (hi & lo) ----
        #pragma unroll
        for (int it = 0; it < 8; it++) {
            const int widx = it * 256 + tid;
            const int m  = widx >> 4;
            const int kw = widx & 15;
            const int gi = woff + (oc0 + m) * 256 + k0 + kw * 2;
            const uint32_t hv = *reinterpret_cast<const uint32_t*>(&g_Whi[gi]);
            const uint32_t lv = *reinterpret_cast<const uint32_t*>(&g_Wlo[gi]);
            *reinterpret_cast<uint32_t*>((char*)sAH + m * 80 + kw * 4) = hv;
            *reinterpret_cast<uint32_t*>((char*)sAL + m * 80 + kw * 4) = lv;
        }
        // ---- B tile: 32 k x 128 pix (hi & lo) ----
        #pragma unroll
        for (int it = 0; it < 16; it++) {
            const int idx = it * 256 + tid;
            const int c   = idx >> 7;
            const int pix = idx & 127;
            float v = 0.f;
            if (MODE == 2) {
                v = g_ATT[((b * 256 + k0 + c) << 16) + (h << 8) + w0 + pix];
            } else {
                const int w = w0 + pix;
                if (h < HH && w < WW)
                    v = X[((size_t)(b * 256 + k0 + c) * HH + h) * WW + w];
            }
            const __nv_bfloat16 hi = __float2bfloat16(v);
            sBH[c * 136 + pix] = hi;
            sBL[c * 136 + pix] = __float2bfloat16(v - __bfloat162float(hi));
        }
        __syncthreads();

        #pragma unroll
        for (int s = 0; s < 2; s++) {          // two k16 steps
            uint32_t bh[4][4], bl[4][4];
            #pragma unroll
            for (int np = 0; np < 4; np++) {
                const uint32_t bo = bLaneOff + (uint32_t)(s * 16 * 272 + np * 32);
                LDSM_X4_T(bh[np][0], bh[np][1], bh[np][2], bh[np][3], uBH + bo);
                LDSM_X4_T(bl[np][0], bl[np][1], bl[np][2], bl[np][3], uBL + bo);
            }
            #pragma unroll
            for (int mt = 0; mt < 2; mt++) {
                uint32_t ah[4], al[4];
                const uint32_t ao = aLaneOff + (uint32_t)(mt * 16 * 80 + s * 32);
                LDSM_X4(ah[0], ah[1], ah[2], ah[3], uAH + ao);
                LDSM_X4(al[0], al[1], al[2], al[3], uAL + ao);
                #pragma unroll
                for (int np = 0; np < 4; np++) {
                    #pragma unroll
                    for (int half = 0; half < 2; half++) {
                        float* d = acc[mt][np * 2 + half];
                        const uint32_t b0h = bh[np][half * 2], b1h = bh[np][half * 2 + 1];
                        const uint32_t b0l = bl[np][half * 2], b1l = bl[np][half * 2 + 1];
                        mma_bf16(d, ah, b0h, b1h);
                        mma_bf16(d, ah, b0l, b1l);
                        mma_bf16(d, al, b0h, b1h);
                    }
                }
            }
        }
        __syncthreads();
    }

    // ---- epilogue ----
    float* dst = (MODE == 0) ? g_Q : ((oc0 < 256) ? g_K : g_V);

    #pragma unroll
    for (int mt = 0; mt < 2; mt++) {
        const int mBase = warp_m * 32 + mt * 16 + (lane >> 2);
        #pragma unroll
        for (int oct = 0; oct < 8; oct++) {
            const int n = warp_n * 64 + oct * 8 + 2 * (lane & 3);
            const float* d = acc[mt][oct];
            #pragma unroll
            for (int rr = 0; rr < 2; rr++) {   // rr=0: rows m, rr=1: m+8
                const int oc = oc0 + mBase + rr * 8;
                const float v0 = d[rr * 2 + 0];
                const float v1 = d[rr * 2 + 1];
                if (MODE == 2) {
                    const float bs = bias[oc];
                    const int w = w0 + n;
                    if (h < HH) {
                        if (w < WW)
                            Out[((size_t)(b * 256 + oc) * HH + h) * WW + w] = v0 + bs;
                        if (w + 1 < WW)
                            Out[((size_t)(b * 256 + oc) * HH + h) * WW + w + 1] = v1 + bs;
                    }
                } else {
                    const int w  = w0 + n;
                    const int nw = (b * 32 + (h >> 3)) * 32 + (w >> 3);
                    const int l  = ((h & 7) << 3) | (w & 7);
                    const int cc = oc & 255;
                    float2 v; v.x = v0; v.y = v1;
                    *reinterpret_cast<float2*>(
                        &dst[(((nw * 8 + (cc >> 5)) * 32 + (cc & 31)) << 6) + l]) = v;
                }
            }
        }
    }
}

// ---------------------------------------------------------------------------
// Attention v2: 128 threads, 2 (window,head) pairs per block.
// Thread owns query row l; logits s[64] in regs; K/V read via LDS.128.
// ---------------------------------------------------------------------------
__global__ __launch_bounds__(128)
void attn_kernel()
{
    __shared__ float Ks[2][2048];
    __shared__ float Vs[2][2048];

    const int tid  = threadIdx.x;
    const int half = tid >> 6;
    const int l    = tid & 63;
    const int nb   = blockIdx.x * 2 + half;
    const size_t base = (size_t)nb * 2048;

    for (int i = l; i < 2048; i += 64) {
        Ks[half][i] = g_K[base + i];
        Vs[half][i] = g_V[base + i];
    }
    __syncthreads();

    float q[32];
    #pragma unroll
    for (int d = 0; d < 32; d++) q[d] = g_Q[base + d * 64 + l];

    float s[64];
    #pragma unroll
    for (int m = 0; m < 64; m++) s[m] = 0.f;

    #pragma unroll
    for (int d = 0; d < 32; d++) {
        const float qd = q[d];
        const float4* kp = reinterpret_cast<const float4*>(&Ks[half][d << 6]);
        #pragma unroll
        for (int m4 = 0; m4 < 16; m4++) {
            const float4 kv = kp[m4];
            s[m4 * 4 + 0] += qd * kv.x;
            s[m4 * 4 + 1] += qd * kv.y;
            s[m4 * 4 + 2] += qd * kv.z;
            s[m4 * 4 + 3] += qd * kv.w;
        }
    }

    const float scale = 0.1767766952966369f;
    float mx = -1e30f;
    #pragma unroll
    for (int m = 0; m < 64; m++) { s[m] *= scale; mx = fmaxf(mx, s[m]); }
    float sum = 0.f;
    #pragma unroll
    for (int m = 0; m < 64; m++) { s[m] = __expf(s[m] - mx); sum += s[m]; }
    const float inv = 1.f / sum;
    #pragma unroll
    for (int m = 0; m < 64; m++) s[m] *= inv;

    const int n = nb >> 3, head = nb & 7;
    const int b  = n >> 10;
    const int hw = (n >> 5) & 31;
    const int ww = n & 31;
    const int h = hw * 8 + (l >> 3);
    const int w = ww * 8 + (l & 7);
    float* outp = g_ATT + ((size_t)(b * 256 + head * 32) << 16) + (h << 8) + w;

    #pragma unroll 1
    for (int d = 0; d < 32; d++) {
        const float4* vp = reinterpret_cast<const float4*>(&Vs[half][d << 6]);
        float a = 0.f;
        #pragma unroll
        for (int m4 = 0; m4 < 16; m4++) {
            const float4 vv = vp[m4];
            a += s[m4 * 4 + 0] * vv.x;
            a += s[m4 * 4 + 1] * vv.y;
            a += s[m4 * 4 + 2] * vv.z;
            a += s[m4 * 4 + 3] * vv.w;
        }
        outp[(size_t)d << 16] = a;
    }
}

// ---------------------------------------------------------------------------
extern "C" void kernel_launch(void* const* d_in, const int* in_sizes, int n_in,
                              void* d_out, int out_size)
{
    const float* x_q    = (const float*)d_in[0];
    const float* x_kv   = (const float*)d_in[1];
    const float* w_q    = (const float*)d_in[2];
    const float* w_kv   = (const float*)d_in[3];
    const float* w_proj = (const float*)d_in[4];
    const float* b_proj = (const float*)d_in[5];
    float* out = (float*)d_out;

    prep_w<<<1024, 256>>>(w_q, w_kv, w_proj);

    const int pixTiles = (BB * HP * WP) / 128;   // 2048
    proj_mma<0><<<dim3(pixTiles, 2), 256>>>(x_q,  0,      nullptr, nullptr);
    proj_mma<1><<<dim3(pixTiles, 4), 256>>>(x_kv, 65536,  nullptr, nullptr);
    attn_kernel<<<16384, 128>>>();
    proj_mma<2><<<dim3(pixTiles, 2), 256>>>(nullptr, 196608, b_proj, out);
}

// round 4
// speedup vs baseline: 1.7649x; 1.0905x over previous
#include <cuda_runtime.h>
#include <cuda_bf16.h>
#include <cstdint>
#include <math.h>

// Problem constants
#define BB 4
#define CC 256
#define HH 252
#define WW 252
#define HP 256
#define WP 256

// Q/K/V in split-bf16, layout [wh=32768][d=32][pix=64]  (wh = window*8 + head)
__device__ __nv_bfloat16 g_Qh[67108864];
__device__ __nv_bfloat16 g_Ql[67108864];
__device__ __nv_bfloat16 g_Kh[67108864];
__device__ __nv_bfloat16 g_Kl[67108864];
__device__ __nv_bfloat16 g_Vh[67108864];
__device__ __nv_bfloat16 g_Vl[67108864];
__device__ float g_ATT[4 * 256 * 256 * 256];   // padded image [B][C][256][256]

// Pre-split weights (bf16 hi/lo): wq(256x256) | wkv(512x256) | wproj(256x256)
__device__ __nv_bfloat16 g_Whi[262144];
__device__ __nv_bfloat16 g_Wlo[262144];

// ---------------------------------------------------------------------------
__device__ __forceinline__ uint32_t smem_u32(const void* p) {
    uint32_t a;
    asm("{ .reg .u64 t; cvta.to.shared.u64 t, %1; cvt.u32.u64 %0, t; }"
        : "=r"(a) : "l"(p));
    return a;
}
#define LDSM_X4(r0, r1, r2, r3, addr)                                          \
    asm volatile("ldmatrix.sync.aligned.m8n8.x4.shared.b16 {%0,%1,%2,%3}, [%4];" \
                 : "=r"(r0), "=r"(r1), "=r"(r2), "=r"(r3) : "r"(addr))
#define LDSM_X4_T(r0, r1, r2, r3, addr)                                        \
    asm volatile("ldmatrix.sync.aligned.m8n8.x4.trans.shared.b16 {%0,%1,%2,%3}, [%4];" \
                 : "=r"(r0), "=r"(r1), "=r"(r2), "=r"(r3) : "r"(addr))

__device__ __forceinline__ void mma_bf16(float* d, const uint32_t* a,
                                         uint32_t b0, uint32_t b1) {
    asm volatile(
        "mma.sync.aligned.m16n8k16.row.col.f32.bf16.bf16.f32 "
        "{%0,%1,%2,%3}, {%4,%5,%6,%7}, {%8,%9}, {%0,%1,%2,%3};"
        : "+f"(d[0]), "+f"(d[1]), "+f"(d[2]), "+f"(d[3])
        : "r"(a[0]), "r"(a[1]), "r"(a[2]), "r"(a[3]), "r"(b0), "r"(b1));
}
__device__ __forceinline__ uint32_t pack_bf16(float lo, float hi) {
    __nv_bfloat162 v;
    v.x = __float2bfloat16(lo);
    v.y = __float2bfloat16(hi);
    return *reinterpret_cast<uint32_t*>(&v);
}

// ---------------------------------------------------------------------------
// Weight prep: fp32 -> (hi, lo) bf16 split.
// ---------------------------------------------------------------------------
__global__ void prep_w(const float* __restrict__ wq, const float* __restrict__ wkv,
                       const float* __restrict__ wproj)
{
    int i = blockIdx.x * 256 + threadIdx.x;
    float v;
    if (i < 65536)       v = wq[i];
    else if (i < 196608) v = wkv[i - 65536];
    else                 v = wproj[i - 196608];
    __nv_bfloat16 hi = __float2bfloat16(v);
    g_Whi[i] = hi;
    g_Wlo[i] = __float2bfloat16(v - __bfloat162float(hi));
}

// ---------------------------------------------------------------------------
// HMMA projection GEMM (as R3). MODE0/1 epilogue now emits split-bf16 QKV.
// ---------------------------------------------------------------------------
template <int MODE>
__global__ __launch_bounds__(256)
void proj_mma(const float* __restrict__ X, int woff,
              const float* __restrict__ bias, float* __restrict__ Out)
{
    __shared__ __nv_bfloat16 sAH[128 * 40];
    __shared__ __nv_bfloat16 sAL[128 * 40];
    __shared__ __nv_bfloat16 sBH[32 * 136];
    __shared__ __nv_bfloat16 sBL[32 * 136];

    const int tid  = threadIdx.x;
    const int wid  = tid >> 5;
    const int lane = tid & 31;
    const int warp_m = wid & 3;
    const int warp_n = wid >> 2;

    const int p0  = blockIdx.x * 128;
    const int oc0 = blockIdx.y * 128;
    const int b   = p0 >> 16;
    const int rem = p0 & 65535;
    const int h   = rem >> 8;
    const int w0  = rem & 255;

    const uint32_t uAH = smem_u32(sAH);
    const uint32_t uAL = smem_u32(sAL);
    const uint32_t uBH = smem_u32(sBH);
    const uint32_t uBL = smem_u32(sBL);

    float acc[2][8][4];
    #pragma unroll
    for (int i = 0; i < 2; i++)
        #pragma unroll
        for (int j = 0; j < 8; j++)
            #pragma unroll
            for (int k = 0; k < 4; k++) acc[i][j][k] = 0.f;

    const uint32_t aLaneOff = (uint32_t)((warp_m * 32 + (lane & 15)) * 80 + (lane >> 4) * 16);
    const uint32_t bLaneOff = (uint32_t)(((lane & 7) + ((lane >> 3) & 1) * 8) * 272
                                         + (warp_n * 64 + (lane >> 4) * 8) * 2);

    for (int ch = 0; ch < 8; ch++) {
        const int k0 = ch * 32;
        #pragma unroll
        for (int it = 0; it < 8; it++) {
            const int widx = it * 256 + tid;
            const int m  = widx >> 4;
            const int kw = widx & 15;
            const int gi = woff + (oc0 + m) * 256 + k0 + kw * 2;
            const uint32_t hv = *reinterpret_cast<const uint32_t*>(&g_Whi[gi]);
            const uint32_t lv = *reinterpret_cast<const uint32_t*>(&g_Wlo[gi]);
            *reinterpret_cast<uint32_t*>((char*)sAH + m * 80 + kw * 4) = hv;
            *reinterpret_cast<uint32_t*>((char*)sAL + m * 80 + kw * 4) = lv;
        }
        #pragma unroll
        for (int it = 0; it < 16; it++) {
            const int idx = it * 256 + tid;
            const int c   = idx >> 7;
            const int pix = idx & 127;
            float v = 0.f;
            if (MODE == 2) {
                v = g_ATT[((b * 256 + k0 + c) << 16) + (h << 8) + w0 + pix];
            } else {
                const int w = w0 + pix;
                if (h < HH && w < WW)
                    v = X[((size_t)(b * 256 + k0 + c) * HH + h) * WW + w];
            }
            const __nv_bfloat16 hi = __float2bfloat16(v);
            sBH[c * 136 + pix] = hi;
            sBL[c * 136 + pix] = __float2bfloat16(v - __bfloat162float(hi));
        }
        __syncthreads();

        #pragma unroll
        for (int s = 0; s < 2; s++) {
            uint32_t bh[4][4], bl[4][4];
            #pragma unroll
            for (int np = 0; np < 4; np++) {
                const uint32_t bo = bLaneOff + (uint32_t)(s * 16 * 272 + np * 32);
                LDSM_X4_T(bh[np][0], bh[np][1], bh[np][2], bh[np][3], uBH + bo);
                LDSM_X4_T(bl[np][0], bl[np][1], bl[np][2], bl[np][3], uBL + bo);
            }
            #pragma unroll
            for (int mt = 0; mt < 2; mt++) {
                uint32_t ah[4], al[4];
                const uint32_t ao = aLaneOff + (uint32_t)(mt * 16 * 80 + s * 32);
                LDSM_X4(ah[0], ah[1], ah[2], ah[3], uAH + ao);
                LDSM_X4(al[0], al[1], al[2], al[3], uAL + ao);
                #pragma unroll
                for (int np = 0; np < 4; np++) {
                    #pragma unroll
                    for (int half = 0; half < 2; half++) {
                        float* d = acc[mt][np * 2 + half];
                        const uint32_t b0h = bh[np][half * 2], b1h = bh[np][half * 2 + 1];
                        const uint32_t b0l = bl[np][half * 2], b1l = bl[np][half * 2 + 1];
                        mma_bf16(d, ah, b0h, b1h);
                        mma_bf16(d, ah, b0l, b1l);
                        mma_bf16(d, al, b0h, b1h);
                    }
                }
            }
        }
        __syncthreads();
    }

    // ---- epilogue ----
    #pragma unroll
    for (int mt = 0; mt < 2; mt++) {
        const int mBase = warp_m * 32 + mt * 16 + (lane >> 2);
        #pragma unroll
        for (int oct = 0; oct < 8; oct++) {
            const int n = warp_n * 64 + oct * 8 + 2 * (lane & 3);
            const float* d = acc[mt][oct];
            #pragma unroll
            for (int rr = 0; rr < 2; rr++) {
                const int oc = oc0 + mBase + rr * 8;
                float v0 = d[rr * 2 + 0];
                float v1 = d[rr * 2 + 1];
                if (MODE == 2) {
                    const float bs = bias[oc];
                    const int w = w0 + n;
                    if (h < HH) {
                        if (w < WW)
                            Out[((size_t)(b * 256 + oc) * HH + h) * WW + w] = v0 + bs;
                        if (w + 1 < WW)
                            Out[((size_t)(b * 256 + oc) * HH + h) * WW + w + 1] = v1 + bs;
                    }
                } else {
                    if (MODE == 0) {
                        v0 *= 0.1767766952966369f;   // fold softmax scale into Q
                        v1 *= 0.1767766952966369f;
                    }
                    const int w  = w0 + n;
                    const int nw = (b * 32 + (h >> 3)) * 32 + (w >> 3);
                    const int l  = ((h & 7) << 3) | (w & 7);      // even
                    const int cc = oc & 255;
                    const int dch  = cc & 31;
                    const int head = cc >> 5;
                    const int idx2 = (((nw * 8 + head) * 32 + dch) * 64 + l) >> 1;
                    const __nv_bfloat16 h0 = __float2bfloat16(v0);
                    const __nv_bfloat16 h1 = __float2bfloat16(v1);
                    __nv_bfloat162 ph, pl;
                    ph.x = h0; ph.y = h1;
                    pl.x = __float2bfloat16(v0 - __bfloat162float(h0));
                    pl.y = __float2bfloat16(v1 - __bfloat162float(h1));
                    __nv_bfloat162* dh;
                    __nv_bfloat162* dl;
                    if (MODE == 0) {
                        dh = reinterpret_cast<__nv_bfloat162*>(g_Qh);
                        dl = reinterpret_cast<__nv_bfloat162*>(g_Ql);
                    } else if (oc0 < 256) {
                        dh = reinterpret_cast<__nv_bfloat162*>(g_Kh);
                        dl = reinterpret_cast<__nv_bfloat162*>(g_Kl);
                    } else {
                        dh = reinterpret_cast<__nv_bfloat162*>(g_Vh);
                        dl = reinterpret_cast<__nv_bfloat162*>(g_Vl);
                    }
                    dh[idx2] = ph;
                    dl[idx2] = pl;
                }
            }
        }
    }
}

// ---------------------------------------------------------------------------
// MMA attention: block = 128 threads = 2 window-heads, 2 warps per wh.
// Slabs [d=32][pix=64] bf16, smem pitch 144B. Full 3-term split both GEMMs.
// ---------------------------------------------------------------------------
#define SLAB 4608                 // 32 rows * 144B
#define WHSZ (6 * SLAB)           // Qh Ql Kh Kl Vh Vl
#define ATT_SMEM (2 * WHSZ)       // 55296

__global__ __launch_bounds__(128)
void attn_mma()
{
    extern __shared__ char smem[];
    const int tid  = threadIdx.x;
    const int wid  = tid >> 5;
    const int lane = tid & 31;

    // ---- stage 2 wh x 6 slabs ----
    const __nv_bfloat16* srcs[6] = {g_Qh, g_Ql, g_Kh, g_Kl, g_Vh, g_Vl};
    #pragma unroll
    for (int sl = 0; sl < 2; sl++) {
        const size_t gbase = (size_t)(blockIdx.x * 2 + sl) * 2048;
        #pragma unroll
        for (int a = 0; a < 6; a++) {
            const uint4* src = reinterpret_cast<const uint4*>(srcs[a] + gbase);
            char* dstb = smem + sl * WHSZ + a * SLAB;
            #pragma unroll
            for (int i = 0; i < 2; i++) {
                const int idx = i * 128 + tid;           // 0..255 uint4
                const uint4 v = src[idx];
                *reinterpret_cast<uint4*>(dstb + (idx >> 3) * 144 + (idx & 7) * 16) = v;
            }
        }
    }
    __syncthreads();

    const uint32_t sb  = smem_u32(smem) + (wid >> 1) * WHSZ;
    const uint32_t uQh = sb,            uQl = sb + SLAB;
    const uint32_t uKh = sb + 2 * SLAB, uKl = sb + 3 * SLAB;
    const uint32_t uVh = sb + 4 * SLAB, uVl = sb + 5 * SLAB;
    const int whalf = wid & 1;
    const int wh = blockIdx.x * 2 + (wid >> 1);

    const int g = lane >> 2;
    const int t = lane & 3;

    // output address pieces
    const int n    = wh >> 3;
    const int head = wh & 7;
    const int b    = n >> 10;
    const int hw   = (n >> 5) & 31;
    const int wwin = n & 31;

    // lane addressing (in bytes)
    const uint32_t qRow = (uint32_t)((lane & 7) + ((lane >> 4) & 1) * 8);
    const uint32_t qCol = (uint32_t)(((lane >> 3) & 1) * 16);
    const uint32_t kRow = (uint32_t)((lane & 7) + ((lane >> 3) & 1) * 8);
    const uint32_t kCol = (uint32_t)((lane >> 4) * 16);
    const uint32_t vRow = (uint32_t)((lane & 7) + ((lane >> 4) & 1) * 8);
    const uint32_t vCol = (uint32_t)(((lane >> 3) & 1) * 16);

    #pragma unroll
    for (int mt = 0; mt < 2; mt++) {
        const int ltile = whalf * 2 + mt;               // 16-row l tile

        // ---- S = (Q^T)(K): rows l (16), cols m (64), k = d (32) ----
        float s[8][4];
        #pragma unroll
        for (int j = 0; j < 8; j++)
            #pragma unroll
            for (int k = 0; k < 4; k++) s[j][k] = 0.f;

        #pragma unroll
        for (int kt = 0; kt < 2; kt++) {
            uint32_t ah[4], al[4];
            const uint32_t ao = (qRow + kt * 16) * 144 + qCol + (uint32_t)(ltile * 32);
            LDSM_X4_T(ah[0], ah[1], ah[2], ah[3], uQh + ao);
            LDSM_X4_T(al[0], al[1], al[2], al[3], uQl + ao);
            #pragma unroll
            for (int nt = 0; nt < 4; nt++) {
                uint32_t bh[4], bl[4];
                const uint32_t bo = (kRow + kt * 16) * 144 + kCol + (uint32_t)(nt * 32);
                LDSM_X4_T(bh[0], bh[1], bh[2], bh[3], uKh + bo);
                LDSM_X4_T(bl[0], bl[1], bl[2], bl[3], uKl + bo);
                #pragma unroll
                for (int half = 0; half < 2; half++) {
                    float* d = s[nt * 2 + half];
                    mma_bf16(d, ah, bh[half * 2], bh[half * 2 + 1]);
                    mma_bf16(d, ah, bl[half * 2], bl[half * 2 + 1]);
                    mma_bf16(d, al, bh[half * 2], bh[half * 2 + 1]);
                }
            }
        }

        // ---- fragment softmax (rows g and g+8) ----
        float mx0 = -1e30f, mx1 = -1e30f;
        #pragma unroll
        for (int j = 0; j < 8; j++) {
            mx0 = fmaxf(mx0, fmaxf(s[j][0], s[j][1]));
            mx1 = fmaxf(mx1, fmaxf(s[j][2], s[j][3]));
        }
        mx0 = fmaxf(mx0, __shfl_xor_sync(0xffffffffu, mx0, 1));
        mx0 = fmaxf(mx0, __shfl_xor_sync(0xffffffffu, mx0, 2));
        mx1 = fmaxf(mx1, __shfl_xor_sync(0xffffffffu, mx1, 1));
        mx1 = fmaxf(mx1, __shfl_xor_sync(0xffffffffu, mx1, 2));

        float sum0 = 0.f, sum1 = 0.f;
        uint32_t ph01[8], ph23[8], pl01[8], pl23[8];
        #pragma unroll
        for (int j = 0; j < 8; j++) {
            const float e0 = __expf(s[j][0] - mx0);
            const float e1 = __expf(s[j][1] - mx0);
            const float e2 = __expf(s[j][2] - mx1);
            const float e3 = __expf(s[j][3] - mx1);
            sum0 += e0 + e1;
            sum1 += e2 + e3;
            ph01[j] = pack_bf16(e0, e1);
            ph23[j] = pack_bf16(e2, e3);
            const __nv_bfloat162 h01 = *reinterpret_cast<const __nv_bfloat162*>(&ph01[j]);
            const __nv_bfloat162 h23 = *reinterpret_cast<const __nv_bfloat162*>(&ph23[j]);
            pl01[j] = pack_bf16(e0 - __bfloat162float(h01.x), e1 - __bfloat162float(h01.y));
            pl23[j] = pack_bf16(e2 - __bfloat162float(h23.x), e3 - __bfloat162float(h23.y));
        }
        sum0 += __shfl_xor_sync(0xffffffffu, sum0, 1);
        sum0 += __shfl_xor_sync(0xffffffffu, sum0, 2);
        sum1 += __shfl_xor_sync(0xffffffffu, sum1, 1);
        sum1 += __shfl_xor_sync(0xffffffffu, sum1, 2);
        const float inv0 = 1.f / sum0;
        const float inv1 = 1.f / sum1;

        // ---- O = P V: rows l (16), cols d (32), k = m (64) ----
        float o[4][4];
        #pragma unroll
        for (int j = 0; j < 4; j++)
            #pragma unroll
            for (int k = 0; k < 4; k++) o[j][k] = 0.f;

        #pragma unroll
        for (int kt = 0; kt < 4; kt++) {
            uint32_t ap[4], alo[4];
            ap[0]  = ph01[2 * kt];     ap[1]  = ph23[2 * kt];
            ap[2]  = ph01[2 * kt + 1]; ap[3]  = ph23[2 * kt + 1];
            alo[0] = pl01[2 * kt];     alo[1] = pl23[2 * kt];
            alo[2] = pl01[2 * kt + 1]; alo[3] = pl23[2 * kt + 1];
            #pragma unroll
            for (int dt2 = 0; dt2 < 2; dt2++) {
                uint32_t bh[4], bl[4];
                const uint32_t bo = (vRow + dt2 * 16) * 144 + vCol + (uint32_t)(kt * 32);
                LDSM_X4(bh[0], bh[1], bh[2], bh[3], uVh + bo);
                LDSM_X4(bl[0], bl[1], bl[2], bl[3], uVl + bo);
                #pragma unroll
                for (int half = 0; half < 2; half++) {
                    float* d = o[dt2 * 2 + half];
                    mma_bf16(d, ap, bh[half * 2], bh[half * 2 + 1]);
                    mma_bf16(d, ap, bl[half * 2], bl[half * 2 + 1]);
                    mma_bf16(d, alo, bh[half * 2], bh[half * 2 + 1]);
                }
            }
        }

        // ---- store to padded image ----
        const int l0 = ltile * 16 + g;
        const int l1 = l0 + 8;
        const int h0 = hw * 8 + (l0 >> 3), w0p = wwin * 8 + (l0 & 7);
        const int h1 = hw * 8 + (l1 >> 3), w1p = wwin * 8 + (l1 & 7);
        #pragma unroll
        for (int dt = 0; dt < 4; dt++) {
            const int c = head * 32 + dt * 8 + 2 * t;
            float* p0 = g_ATT + ((size_t)(b * 256 + c) << 16);
            g_ATT[((b * 256 + c) << 16)     + (h0 << 8) + w0p] = o[dt][0] * inv0;
            g_ATT[((b * 256 + c + 1) << 16) + (h0 << 8) + w0p] = o[dt][1] * inv0;
            g_ATT[((b * 256 + c) << 16)     + (h1 << 8) + w1p] = o[dt][2] * inv1;
            g_ATT[((b * 256 + c + 1) << 16) + (h1 << 8) + w1p] = o[dt][3] * inv1;
            (void)p0;
        }
    }
}

// ---------------------------------------------------------------------------
extern "C" void kernel_launch(void* const* d_in, const int* in_sizes, int n_in,
                              void* d_out, int out_size)
{
    const float* x_q    = (const float*)d_in[0];
    const float* x_kv   = (const float*)d_in[1];
    const float* w_q    = (const float*)d_in[2];
    const float* w_kv   = (const float*)d_in[3];
    const float* w_proj = (const float*)d_in[4];
    const float* b_proj = (const float*)d_in[5];
    float* out = (float*)d_out;

    cudaFuncSetAttribute(attn_mma, cudaFuncAttributeMaxDynamicSharedMemorySize, ATT_SMEM);

    prep_w<<<1024, 256>>>(w_q, w_kv, w_proj);

    const int pixTiles = (BB * HP * WP) / 128;   // 2048
    proj_mma<0><<<dim3(pixTiles, 2), 256>>>(x_q,  0,      nullptr, nullptr);
    proj_mma<1><<<dim3(pixTiles, 4), 256>>>(x_kv, 65536,  nullptr, nullptr);
    attn_mma<<<16384, 128, ATT_SMEM>>>();
    proj_mma<2><<<dim3(pixTiles, 2), 256>>>(nullptr, 196608, b_proj, out);
}

// round 5
// speedup vs baseline: 3.0189x; 1.7104x over previous
#include <cuda_runtime.h>
#include <cuda_bf16.h>
#include <cstdint>
#include <math.h>

// Problem constants
#define BB 4
#define CC 256
#define HH 252
#define WW 252
#define HP 256
#define WP 256

// Q/K/V split-bf16, layout [wh=32768][d=32][pix=64]
__device__ __nv_bfloat16 g_Qh[67108864];
__device__ __nv_bfloat16 g_Ql[67108864];
__device__ __nv_bfloat16 g_Kh[67108864];
__device__ __nv_bfloat16 g_Kl[67108864];
__device__ __nv_bfloat16 g_Vh[67108864];
__device__ __nv_bfloat16 g_Vl[67108864];
// Padded bf16 images [B][C][256][256] (split hi/lo): inputs and attention out
__device__ __nv_bfloat16 g_Xqh[67108864];
__device__ __nv_bfloat16 g_Xql[67108864];
__device__ __nv_bfloat16 g_Xkh[67108864];
__device__ __nv_bfloat16 g_Xkl[67108864];
__device__ __nv_bfloat16 g_Ah[67108864];
__device__ __nv_bfloat16 g_Al[67108864];
// Pre-split weights: wq(256x256) | wkv(512x256) | wproj(256x256)
__device__ __nv_bfloat16 g_Whi[262144];
__device__ __nv_bfloat16 g_Wlo[262144];

// ---------------------------------------------------------------------------
__device__ __forceinline__ uint32_t smem_u32(const void* p) {
    uint32_t a;
    asm("{ .reg .u64 t; cvta.to.shared.u64 t, %1; cvt.u32.u64 %0, t; }"
        : "=r"(a) : "l"(p));
    return a;
}
#define LDSM_X4(r0, r1, r2, r3, addr)                                          \
    asm volatile("ldmatrix.sync.aligned.m8n8.x4.shared.b16 {%0,%1,%2,%3}, [%4];" \
                 : "=r"(r0), "=r"(r1), "=r"(r2), "=r"(r3) : "r"(addr))
#define LDSM_X4_T(r0, r1, r2, r3, addr)                                        \
    asm volatile("ldmatrix.sync.aligned.m8n8.x4.trans.shared.b16 {%0,%1,%2,%3}, [%4];" \
                 : "=r"(r0), "=r"(r1), "=r"(r2), "=r"(r3) : "r"(addr))
__device__ __forceinline__ void mma_bf16(float* d, const uint32_t* a,
                                         uint32_t b0, uint32_t b1) {
    asm volatile(
        "mma.sync.aligned.m16n8k16.row.col.f32.bf16.bf16.f32 "
        "{%0,%1,%2,%3}, {%4,%5,%6,%7}, {%8,%9}, {%0,%1,%2,%3};"
        : "+f"(d[0]), "+f"(d[1]), "+f"(d[2]), "+f"(d[3])
        : "r"(a[0]), "r"(a[1]), "r"(a[2]), "r"(a[3]), "r"(b0), "r"(b1));
}
__device__ __forceinline__ uint32_t pack_bf16(float lo, float hi) {
    __nv_bfloat162 v;
    v.x = __float2bfloat16(lo);
    v.y = __float2bfloat16(hi);
    return *reinterpret_cast<uint32_t*>(&v);
}
__device__ __forceinline__ void cpa16(uint32_t dst, const void* src) {
    asm volatile("cp.async.cg.shared.global [%0], [%1], 16;" :: "r"(dst), "l"(src));
}
#define CP_COMMIT() asm volatile("cp.async.commit_group;" ::: "memory")
#define CP_WAIT(n)  asm volatile("cp.async.wait_group %0;" :: "n"(n) : "memory")

// ---------------------------------------------------------------------------
__global__ void prep_w(const float* __restrict__ wq, const float* __restrict__ wkv,
                       const float* __restrict__ wproj)
{
    int i = blockIdx.x * 256 + threadIdx.x;
    float v;
    if (i < 65536)       v = wq[i];
    else if (i < 196608) v = wkv[i - 65536];
    else                 v = wproj[i - 196608];
    __nv_bfloat16 hi = __float2bfloat16(v);
    g_Whi[i] = hi;
    g_Wlo[i] = __float2bfloat16(v - __bfloat162float(hi));
}

// Split x_q / x_kv into zero-padded bf16 hi/lo images. 4 elems/thread.
__global__ __launch_bounds__(256)
void prep_x(const float* __restrict__ xq, const float* __restrict__ xkv)
{
    const long long i4 = ((long long)blockIdx.x * 256 + threadIdx.x) * 4;
    const int which = (i4 >= 67108864LL);                // 0: xq, 1: xkv
    const int idx   = (int)(i4 & 67108863LL);            // within padded image
    const int bc = idx >> 16;
    const int hp = (idx >> 8) & 255;
    const int wp = idx & 255;
    float4 v = make_float4(0.f, 0.f, 0.f, 0.f);
    if (hp < HH && wp < WW) {
        const float* src = which ? xkv : xq;
        v = *reinterpret_cast<const float4*>(
            &src[((size_t)bc * HH + hp) * WW + wp]);
    }
    uint2 ph, pl;
    {
        __nv_bfloat162 a, b;
        a.x = __float2bfloat16(v.x); a.y = __float2bfloat16(v.y);
        b.x = __float2bfloat16(v.z); b.y = __float2bfloat16(v.w);
        ph.x = *reinterpret_cast<uint32_t*>(&a);
        ph.y = *reinterpret_cast<uint32_t*>(&b);
        __nv_bfloat162 c, d;
        c.x = __float2bfloat16(v.x - __bfloat162float(a.x));
        c.y = __float2bfloat16(v.y - __bfloat162float(a.y));
        d.x = __float2bfloat16(v.z - __bfloat162float(b.x));
        d.y = __float2bfloat16(v.w - __bfloat162float(b.y));
        pl.x = *reinterpret_cast<uint32_t*>(&c);
        pl.y = *reinterpret_cast<uint32_t*>(&d);
    }
    __nv_bfloat16* dh = which ? g_Xkh : g_Xqh;
    __nv_bfloat16* dl = which ? g_Xkl : g_Xql;
    *reinterpret_cast<uint2*>(dh + idx) = ph;
    *reinterpret_cast<uint2*>(dl + idx) = pl;
}

// ---------------------------------------------------------------------------
// Pipelined projection GEMM. D[oc(128), px(128)] = W X, K=256 (8 chunks of 32).
// All operands pre-split bf16; cp.async 2-stage double buffer.
// MODE 0 -> g_Q*, MODE 1 -> g_K*/g_V*, MODE 2 -> cropped Out + bias.
// ---------------------------------------------------------------------------
#define P_AH 0
#define P_AL 10240
#define P_BH 20480
#define P_BL 29184
#define P_STAGE 37888
#define P_SMEM (2 * P_STAGE)

template <int MODE>
__device__ __forceinline__ void proj_issue(
    uint32_t sbase, int tid, int woff, int oc0, int bimg, int h, int w0, int ch,
    const __nv_bfloat16* Bh, const __nv_bfloat16* Bl)
{
    const int k0 = ch * 32;
    #pragma unroll
    for (int it = 0; it < 2; it++) {
        const int idx = it * 256 + tid;
        const int m = idx >> 2;
        const int j = idx & 3;
        const int src = woff + (oc0 + m) * 256 + k0 + j * 8;
        const uint32_t d = sbase + (uint32_t)(m * 80 + j * 16);
        cpa16(d + P_AH, g_Whi + src);
        cpa16(d + P_AL, g_Wlo + src);
    }
    #pragma unroll
    for (int it = 0; it < 2; it++) {
        const int idx = it * 256 + tid;
        const int c = idx >> 4;
        const int j = idx & 15;
        const int src = ((bimg * 256 + k0 + c) << 16) + (h << 8) + w0 + j * 8;
        const uint32_t d = sbase + (uint32_t)(c * 272 + j * 16);
        cpa16(d + P_BH, Bh + src);
        cpa16(d + P_BL, Bl + src);
    }
}

template <int MODE>
__global__ __launch_bounds__(256, 2)
void proj_v2(const __nv_bfloat16* __restrict__ Bh,
             const __nv_bfloat16* __restrict__ Bl,
             int woff, const float* __restrict__ bias, float* __restrict__ Out)
{
    extern __shared__ char smem[];
    const uint32_t sb = smem_u32(smem);

    const int tid  = threadIdx.x;
    const int wid  = tid >> 5;
    const int lane = tid & 31;
    const int warp_m = wid & 3;
    const int warp_n = wid >> 2;

    const int p0  = blockIdx.x * 128;
    const int oc0 = blockIdx.y * 128;
    const int b   = p0 >> 16;
    const int rem = p0 & 65535;
    const int h   = rem >> 8;
    const int w0  = rem & 255;

    float acc[2][8][4];
    #pragma unroll
    for (int i = 0; i < 2; i++)
        #pragma unroll
        for (int j = 0; j < 8; j++)
            #pragma unroll
            for (int k = 0; k < 4; k++) acc[i][j][k] = 0.f;

    const uint32_t aLaneOff = (uint32_t)((warp_m * 32 + (lane & 15)) * 80 + (lane >> 4) * 16);
    const uint32_t bLaneOff = (uint32_t)(((lane & 7) + ((lane >> 3) & 1) * 8) * 272
                                         + (warp_n * 64 + (lane >> 4) * 8) * 2);

    proj_issue<MODE>(sb, tid, woff, oc0, b, h, w0, 0, Bh, Bl);
    CP_COMMIT();

    for (int ch = 0; ch < 8; ch++) {
        if (ch < 7)
            proj_issue<MODE>(sb + ((ch + 1) & 1) * P_STAGE, tid, woff, oc0, b, h, w0,
                             ch + 1, Bh, Bl);
        CP_COMMIT();
        CP_WAIT(1);
        __syncthreads();

        const uint32_t st  = sb + (ch & 1) * P_STAGE;
        const uint32_t uAH = st + P_AH, uAL = st + P_AL;
        const uint32_t uBH = st + P_BH, uBL = st + P_BL;

        #pragma unroll
        for (int s = 0; s < 2; s++) {
            uint32_t bh[4][4], bl[4][4];
            #pragma unroll
            for (int np = 0; np < 4; np++) {
                const uint32_t bo = bLaneOff + (uint32_t)(s * 16 * 272 + np * 32);
                LDSM_X4_T(bh[np][0], bh[np][1], bh[np][2], bh[np][3], uBH + bo);
                LDSM_X4_T(bl[np][0], bl[np][1], bl[np][2], bl[np][3], uBL + bo);
            }
            #pragma unroll
            for (int mt = 0; mt < 2; mt++) {
                uint32_t ah[4], al[4];
                const uint32_t ao = aLaneOff + (uint32_t)(mt * 16 * 80 + s * 32);
                LDSM_X4(ah[0], ah[1], ah[2], ah[3], uAH + ao);
                LDSM_X4(al[0], al[1], al[2], al[3], uAL + ao);
                #pragma unroll
                for (int np = 0; np < 4; np++) {
                    #pragma unroll
                    for (int half = 0; half < 2; half++) {
                        float* d = acc[mt][np * 2 + half];
                        const uint32_t b0h = bh[np][half * 2], b1h = bh[np][half * 2 + 1];
                        const uint32_t b0l = bl[np][half * 2], b1l = bl[np][half * 2 + 1];
                        mma_bf16(d, ah, b0h, b1h);
                        mma_bf16(d, ah, b0l, b1l);
                        mma_bf16(d, al, b0h, b1h);
                    }
                }
            }
        }
        __syncthreads();
    }

    // ---- epilogue ----
    #pragma unroll
    for (int mt = 0; mt < 2; mt++) {
        const int mBase = warp_m * 32 + mt * 16 + (lane >> 2);
        #pragma unroll
        for (int oct = 0; oct < 8; oct++) {
            const int n = warp_n * 64 + oct * 8 + 2 * (lane & 3);
            const float* d = acc[mt][oct];
            #pragma unroll
            for (int rr = 0; rr < 2; rr++) {
                const int oc = oc0 + mBase + rr * 8;
                float v0 = d[rr * 2 + 0];
                float v1 = d[rr * 2 + 1];
                if (MODE == 2) {
                    const float bs = bias[oc];
                    const int w = w0 + n;
                    if (h < HH) {
                        if (w < WW)
                            Out[((size_t)(b * 256 + oc) * HH + h) * WW + w] = v0 + bs;
                        if (w + 1 < WW)
                            Out[((size_t)(b * 256 + oc) * HH + h) * WW + w + 1] = v1 + bs;
                    }
                } else {
                    if (MODE == 0) {
                        v0 *= 0.1767766952966369f;   // fold softmax scale into Q
                        v1 *= 0.1767766952966369f;
                    }
                    const int w  = w0 + n;
                    const int nw = (b * 32 + (h >> 3)) * 32 + (w >> 3);
                    const int l  = ((h & 7) << 3) | (w & 7);
                    const int cc = oc & 255;
                    const int idx2 = (((nw * 8 + (cc >> 5)) * 32 + (cc & 31)) * 64 + l) >> 1;
                    const __nv_bfloat16 h0 = __float2bfloat16(v0);
                    const __nv_bfloat16 h1 = __float2bfloat16(v1);
                    __nv_bfloat162 ph, pl;
                    ph.x = h0; ph.y = h1;
                    pl.x = __float2bfloat16(v0 - __bfloat162float(h0));
                    pl.y = __float2bfloat16(v1 - __bfloat162float(h1));
                    __nv_bfloat162* dh;
                    __nv_bfloat162* dl;
                    if (MODE == 0) {
                        dh = reinterpret_cast<__nv_bfloat162*>(g_Qh);
                        dl = reinterpret_cast<__nv_bfloat162*>(g_Ql);
                    } else if (oc0 < 256) {
                        dh = reinterpret_cast<__nv_bfloat162*>(g_Kh);
                        dl = reinterpret_cast<__nv_bfloat162*>(g_Kl);
                    } else {
                        dh = reinterpret_cast<__nv_bfloat162*>(g_Vh);
                        dl = reinterpret_cast<__nv_bfloat162*>(g_Vl);
                    }
                    dh[idx2] = ph;
                    dl[idx2] = pl;
                }
            }
        }
    }
}

// ---------------------------------------------------------------------------
// MMA attention (R4 design). Output now written as split-bf16 padded image.
// ---------------------------------------------------------------------------
#define SLAB 4608
#define WHSZ (6 * SLAB)
#define ATT_SMEM (2 * WHSZ)

__global__ __launch_bounds__(128)
void attn_mma()
{
    extern __shared__ char smem[];
    const int tid  = threadIdx.x;
    const int wid  = tid >> 5;
    const int lane = tid & 31;

    const __nv_bfloat16* srcs[6] = {g_Qh, g_Ql, g_Kh, g_Kl, g_Vh, g_Vl};
    #pragma unroll
    for (int sl = 0; sl < 2; sl++) {
        const size_t gbase = (size_t)(blockIdx.x * 2 + sl) * 2048;
        #pragma unroll
        for (int a = 0; a < 6; a++) {
            const uint4* src = reinterpret_cast<const uint4*>(srcs[a] + gbase);
            char* dstb = smem + sl * WHSZ + a * SLAB;
            #pragma unroll
            for (int i = 0; i < 2; i++) {
                const int idx = i * 128 + tid;
                const uint4 v = src[idx];
                *reinterpret_cast<uint4*>(dstb + (idx >> 3) * 144 + (idx & 7) * 16) = v;
            }
        }
    }
    __syncthreads();

    const uint32_t sb  = smem_u32(smem) + (wid >> 1) * WHSZ;
    const uint32_t uQh = sb,            uQl = sb + SLAB;
    const uint32_t uKh = sb + 2 * SLAB, uKl = sb + 3 * SLAB;
    const uint32_t uVh = sb + 4 * SLAB, uVl = sb + 5 * SLAB;
    const int whalf = wid & 1;
    const int wh = blockIdx.x * 2 + (wid >> 1);

    const int g = lane >> 2;
    const int t = lane & 3;

    const int n    = wh >> 3;
    const int head = wh & 7;
    const int b    = n >> 10;
    const int hw   = (n >> 5) & 31;
    const int wwin = n & 31;

    const uint32_t qRow = (uint32_t)((lane & 7) + ((lane >> 4) & 1) * 8);
    const uint32_t qCol = (uint32_t)(((lane >> 3) & 1) * 16);
    const uint32_t kRow = (uint32_t)((lane & 7) + ((lane >> 3) & 1) * 8);
    const uint32_t kCol = (uint32_t)((lane >> 4) * 16);
    const uint32_t vRow = (uint32_t)((lane & 7) + ((lane >> 4) & 1) * 8);
    const uint32_t vCol = (uint32_t)(((lane >> 3) & 1) * 16);

    #pragma unroll
    for (int mt = 0; mt < 2; mt++) {
        const int ltile = whalf * 2 + mt;

        float s[8][4];
        #pragma unroll
        for (int j = 0; j < 8; j++)
            #pragma unroll
            for (int k = 0; k < 4; k++) s[j][k] = 0.f;

        #pragma unroll
        for (int kt = 0; kt < 2; kt++) {
            uint32_t ah[4], al[4];
            const uint32_t ao = (qRow + kt * 16) * 144 + qCol + (uint32_t)(ltile * 32);
            LDSM_X4_T(ah[0], ah[1], ah[2], ah[3], uQh + ao);
            LDSM_X4_T(al[0], al[1], al[2], al[3], uQl + ao);
            #pragma unroll
            for (int nt = 0; nt < 4; nt++) {
                uint32_t bh[4], bl[4];
                const uint32_t bo = (kRow + kt * 16) * 144 + kCol + (uint32_t)(nt * 32);
                LDSM_X4_T(bh[0], bh[1], bh[2], bh[3], uKh + bo);
                LDSM_X4_T(bl[0], bl[1], bl[2], bl[3], uKl + bo);
                #pragma unroll
                for (int half = 0; half < 2; half++) {
                    float* d = s[nt * 2 + half];
                    mma_bf16(d, ah, bh[half * 2], bh[half * 2 + 1]);
                    mma_bf16(d, ah, bl[half * 2], bl[half * 2 + 1]);
                    mma_bf16(d, al, bh[half * 2], bh[half * 2 + 1]);
                }
            }
        }

        float mx0 = -1e30f, mx1 = -1e30f;
        #pragma unroll
        for (int j = 0; j < 8; j++) {
            mx0 = fmaxf(mx0, fmaxf(s[j][0], s[j][1]));
            mx1 = fmaxf(mx1, fmaxf(s[j][2], s[j][3]));
        }
        mx0 = fmaxf(mx0, __shfl_xor_sync(0xffffffffu, mx0, 1));
        mx0 = fmaxf(mx0, __shfl_xor_sync(0xffffffffu, mx0, 2));
        mx1 = fmaxf(mx1, __shfl_xor_sync(0xffffffffu, mx1, 1));
        mx1 = fmaxf(mx1, __shfl_xor_sync(0xffffffffu, mx1, 2));

        float sum0 = 0.f, sum1 = 0.f;
        uint32_t ph01[8], ph23[8], pl01[8], pl23[8];
        #pragma unroll
        for (int j = 0; j < 8; j++) {
            const float e0 = __expf(s[j][0] - mx0);
            const float e1 = __expf(s[j][1] - mx0);
            const float e2 = __expf(s[j][2] - mx1);
            const float e3 = __expf(s[j][3] - mx1);
            sum0 += e0 + e1;
            sum1 += e2 + e3;
            ph01[j] = pack_bf16(e0, e1);
            ph23[j] = pack_bf16(e2, e3);
            const __nv_bfloat162 h01 = *reinterpret_cast<const __nv_bfloat162*>(&ph01[j]);
            const __nv_bfloat162 h23 = *reinterpret_cast<const __nv_bfloat162*>(&ph23[j]);
            pl01[j] = pack_bf16(e0 - __bfloat162float(h01.x), e1 - __bfloat162float(h01.y));
            pl23[j] = pack_bf16(e2 - __bfloat162float(h23.x), e3 - __bfloat162float(h23.y));
        }
        sum0 += __shfl_xor_sync(0xffffffffu, sum0, 1);
        sum0 += __shfl_xor_sync(0xffffffffu, sum0, 2);
        sum1 += __shfl_xor_sync(0xffffffffu, sum1, 1);
        sum1 += __shfl_xor_sync(0xffffffffu, sum1, 2);
        const float inv0 = 1.f / sum0;
        const float inv1 = 1.f / sum1;

        float o[4][4];
        #pragma unroll
        for (int j = 0; j < 4; j++)
            #pragma unroll
            for (int k = 0; k < 4; k++) o[j][k] = 0.f;

        #pragma unroll
        for (int kt = 0; kt < 4; kt++) {
            uint32_t ap[4], alo[4];
            ap[0]  = ph01[2 * kt];     ap[1]  = ph23[2 * kt];
            ap[2]  = ph01[2 * kt + 1]; ap[3]  = ph23[2 * kt + 1];
            alo[0] = pl01[2 * kt];     alo[1] = pl23[2 * kt];
            alo[2] = pl01[2 * kt + 1]; alo[3] = pl23[2 * kt + 1];
            #pragma unroll
            for (int dt2 = 0; dt2 < 2; dt2++) {
                uint32_t bh[4], bl[4];
                const uint32_t bo = (vRow + dt2 * 16) * 144 + vCol + (uint32_t)(kt * 32);
                LDSM_X4(bh[0], bh[1], bh[2], bh[3], uVh + bo);
                LDSM_X4(bl[0], bl[1], bl[2], bl[3], uVl + bo);
                #pragma unroll
                for (int half = 0; half < 2; half++) {
                    float* d = o[dt2 * 2 + half];
                    mma_bf16(d, ap, bh[half * 2], bh[half * 2 + 1]);
                    mma_bf16(d, ap, bl[half * 2], bl[half * 2 + 1]);
                    mma_bf16(d, alo, bh[half * 2], bh[half * 2 + 1]);
                }
            }
        }

        // ---- store split-bf16 to padded image ----
        const int l0 = ltile * 16 + g;
        const int l1 = l0 + 8;
        const int h0 = hw * 8 + (l0 >> 3), w0p = wwin * 8 + (l0 & 7);
        const int h1 = hw * 8 + (l1 >> 3), w1p = wwin * 8 + (l1 & 7);
        #pragma unroll
        for (int dt = 0; dt < 4; dt++) {
            const int c = head * 32 + dt * 8 + 2 * t;
            const int i00 = ((b * 256 + c) << 16)       + (h0 << 8) + w0p;
            const int i10 = ((b * 256 + c + 1) << 16)   + (h0 << 8) + w0p;
            const int i01 = ((b * 256 + c) << 16)       + (h1 << 8) + w1p;
            const int i11 = ((b * 256 + c + 1) << 16)   + (h1 << 8) + w1p;
            const float v00 = o[dt][0] * inv0, v10 = o[dt][1] * inv0;
            const float v01 = o[dt][2] * inv1, v11 = o[dt][3] * inv1;
            const __nv_bfloat16 a0 = __float2bfloat16(v00);
            const __nv_bfloat16 a1 = __float2bfloat16(v10);
            const __nv_bfloat16 a2 = __float2bfloat16(v01);
            const __nv_bfloat16 a3 = __float2bfloat16(v11);
            g_Ah[i00] = a0; g_Al[i00] = __float2bfloat16(v00 - __bfloat162float(a0));
            g_Ah[i10] = a1; g_Al[i10] = __float2bfloat16(v10 - __bfloat162float(a1));
            g_Ah[i01] = a2; g_Al[i01] = __float2bfloat16(v01 - __bfloat162float(a2));
            g_Ah[i11] = a3; g_Al[i11] = __float2bfloat16(v11 - __bfloat162float(a3));
        }
    }
}

// ---------------------------------------------------------------------------
extern "C" void kernel_launch(void* const* d_in, const int* in_sizes, int n_in,
                              void* d_out, int out_size)
{
    const float* x_q    = (const float*)d_in[0];
    const float* x_kv   = (const float*)d_in[1];
    const float* w_q    = (const float*)d_in[2];
    const float* w_kv   = (const float*)d_in[3];
    const float* w_proj = (const float*)d_in[4];
    const float* b_proj = (const float*)d_in[5];
    float* out = (float*)d_out;

    cudaFuncSetAttribute(attn_mma, cudaFuncAttributeMaxDynamicSharedMemorySize, ATT_SMEM);
    cudaFuncSetAttribute(proj_v2<0>, cudaFuncAttributeMaxDynamicSharedMemorySize, P_SMEM);
    cudaFuncSetAttribute(proj_v2<1>, cudaFuncAttributeMaxDynamicSharedMemorySize, P_SMEM);
    cudaFuncSetAttribute(proj_v2<2>, cudaFuncAttributeMaxDynamicSharedMemorySize, P_SMEM);

    __nv_bfloat16 *xqh, *xql, *xkh, *xkl, *ah, *al;
    cudaGetSymbolAddress((void**)&xqh, g_Xqh);
    cudaGetSymbolAddress((void**)&xql, g_Xql);
    cudaGetSymbolAddress((void**)&xkh, g_Xkh);
    cudaGetSymbolAddress((void**)&xkl, g_Xkl);
    cudaGetSymbolAddress((void**)&ah,  g_Ah);
    cudaGetSymbolAddress((void**)&al,  g_Al);

    prep_w<<<1024, 256>>>(w_q, w_kv, w_proj);
    prep_x<<<131072, 256>>>(x_q, x_kv);

    const int pixTiles = (BB * HP * WP) / 128;   // 2048
    proj_v2<0><<<dim3(pixTiles, 2), 256, P_SMEM>>>(xqh, xql, 0,      nullptr, nullptr);
    proj_v2<1><<<dim3(pixTiles, 4), 256, P_SMEM>>>(xkh, xkl, 65536,  nullptr, nullptr);
    attn_mma<<<16384, 128, ATT_SMEM>>>();
    proj_v2<2><<<dim3(pixTiles, 2), 256, P_SMEM>>>(ah, al, 196608, b_proj, out);
}

// round 7
// speedup vs baseline: 6.1588x; 2.0401x over previous
#include <cuda_runtime.h>
#include <cuda_fp16.h>
#include <cstdint>
#include <math.h>

// Problem constants
#define BB 4
#define CC 256
#define HH 252
#define WW 252
#define HP 256
#define WP 256

// Q/K/V fp16, layout [wh=32768][d=32][pix=64]
__device__ __half g_Q[67108864];
__device__ __half g_K[67108864];
__device__ __half g_V[67108864];
// Padded fp16 images [B][C][256][256]: inputs and attention out
__device__ __half g_Xq[67108864];
__device__ __half g_Xk[67108864];
__device__ __half g_A[67108864];
// fp16 weights: wq(256x256) | wkv(512x256) | wproj(256x256)
__device__ __half g_W[262144];

// ---------------------------------------------------------------------------
__device__ __forceinline__ uint32_t smem_u32(const void* p) {
    uint32_t a;
    asm("{ .reg .u64 t; cvta.to.shared.u64 t, %1; cvt.u32.u64 %0, t; }"
        : "=r"(a) : "l"(p));
    return a;
}
#define LDSM_X4(r0, r1, r2, r3, addr)                                          \
    asm volatile("ldmatrix.sync.aligned.m8n8.x4.shared.b16 {%0,%1,%2,%3}, [%4];" \
                 : "=r"(r0), "=r"(r1), "=r"(r2), "=r"(r3) : "r"(addr))
#define LDSM_X4_T(r0, r1, r2, r3, addr)                                        \
    asm volatile("ldmatrix.sync.aligned.m8n8.x4.trans.shared.b16 {%0,%1,%2,%3}, [%4];" \
                 : "=r"(r0), "=r"(r1), "=r"(r2), "=r"(r3) : "r"(addr))
__device__ __forceinline__ void mma_f16(float* d, const uint32_t* a,
                                        uint32_t b0, uint32_t b1) {
    asm volatile(
        "mma.sync.aligned.m16n8k16.row.col.f32.f16.f16.f32 "
        "{%0,%1,%2,%3}, {%4,%5,%6,%7}, {%8,%9}, {%0,%1,%2,%3};"
        : "+f"(d[0]), "+f"(d[1]), "+f"(d[2]), "+f"(d[3])
        : "r"(a[0]), "r"(a[1]), "r"(a[2]), "r"(a[3]), "r"(b0), "r"(b1));
}
__device__ __forceinline__ uint32_t pack_half(float a, float b) {
    __half2 v;
    v.x = __float2half_rn(a);
    v.y = __float2half_rn(b);
    return *reinterpret_cast<uint32_t*>(&v);
}
__device__ __forceinline__ void cpa16(uint32_t dst, const void* src) {
    asm volatile("cp.async.cg.shared.global [%0], [%1], 16;" :: "r"(dst), "l"(src));
}
#define CP_COMMIT() asm volatile("cp.async.commit_group;" ::: "memory")
#define CP_WAIT(n)  asm volatile("cp.async.wait_group %0;" :: "n"(n) : "memory")

// ---------------------------------------------------------------------------
__global__ void prep_w(const float* __restrict__ wq, const float* __restrict__ wkv,
                       const float* __restrict__ wproj)
{
    int i = blockIdx.x * 256 + threadIdx.x;
    float v;
    if (i < 65536)       v = wq[i];
    else if (i < 196608) v = wkv[i - 65536];
    else                 v = wproj[i - 196608];
    g_W[i] = __float2half_rn(v);
}

// Pack x_q / x_kv into zero-padded fp16 images. 4 elems/thread.
__global__ __launch_bounds__(256)
void prep_x(const float* __restrict__ xq, const float* __restrict__ xkv)
{
    const long long i4 = ((long long)blockIdx.x * 256 + threadIdx.x) * 4;
    const int which = (i4 >= 67108864LL);
    const int idx   = (int)(i4 & 67108863LL);
    const int bc = idx >> 16;
    const int hp = (idx >> 8) & 255;
    const int wp = idx & 255;
    float4 v = make_float4(0.f, 0.f, 0.f, 0.f);
    if (hp < HH && wp < WW) {
        const float* src = which ? xkv : xq;
        v = *reinterpret_cast<const float4*>(&src[((size_t)bc * HH + hp) * WW + wp]);
    }
    uint2 p;
    p.x = pack_half(v.x, v.y);
    p.y = pack_half(v.z, v.w);
    __half* dh = which ? g_Xk : g_Xq;
    *reinterpret_cast<uint2*>(dh + idx) = p;
}

// ---------------------------------------------------------------------------
// Pipelined fp16 projection GEMM. D[oc(128), px(128)] = W X, K=256 (8 chunks).
// cp.async 2-stage double buffer. MODE 0 -> g_Q, 1 -> g_K/g_V, 2 -> Out+bias.
// ---------------------------------------------------------------------------
#define P_A 0
#define P_B 10240
#define P_STAGE 18944
#define P_SMEM (2 * P_STAGE)

__device__ __forceinline__ void proj_issue(
    uint32_t sbase, int tid, int woff, int oc0, int bimg, int h, int w0, int ch,
    const __half* B)
{
    const int k0 = ch * 32;
    #pragma unroll
    for (int it = 0; it < 2; it++) {
        const int idx = it * 256 + tid;
        const int m = idx >> 2;
        const int j = idx & 3;
        cpa16(sbase + P_A + (uint32_t)(m * 80 + j * 16),
              g_W + woff + (oc0 + m) * 256 + k0 + j * 8);
    }
    #pragma unroll
    for (int it = 0; it < 2; it++) {
        const int idx = it * 256 + tid;
        const int c = idx >> 4;
        const int j = idx & 15;
        cpa16(sbase + P_B + (uint32_t)(c * 272 + j * 16),
              B + ((bimg * 256 + k0 + c) << 16) + (h << 8) + w0 + j * 8);
    }
}

template <int MODE>
__global__ __launch_bounds__(256, 2)
void proj_v2(const __half* __restrict__ Bimg, int woff,
             const float* __restrict__ bias, float* __restrict__ Out)
{
    extern __shared__ char smem[];
    const uint32_t sb = smem_u32(smem);

    const int tid  = threadIdx.x;
    const int wid  = tid >> 5;
    const int lane = tid & 31;
    const int warp_m = wid & 3;
    const int warp_n = wid >> 2;

    const int p0  = blockIdx.x * 128;
    const int oc0 = blockIdx.y * 128;
    const int b   = p0 >> 16;
    const int rem = p0 & 65535;
    const int h   = rem >> 8;
    const int w0  = rem & 255;

    float acc[2][8][4];
    #pragma unroll
    for (int i = 0; i < 2; i++)
        #pragma unroll
        for (int j = 0; j < 8; j++)
            #pragma unroll
            for (int k = 0; k < 4; k++) acc[i][j][k] = 0.f;

    const uint32_t aLaneOff = (uint32_t)((warp_m * 32 + (lane & 15)) * 80 + (lane >> 4) * 16);
    const uint32_t bLaneOff = (uint32_t)(((lane & 7) + ((lane >> 3) & 1) * 8) * 272
                                         + (warp_n * 64 + (lane >> 4) * 8) * 2);

    proj_issue(sb, tid, woff, oc0, b, h, w0, 0, Bimg);
    CP_COMMIT();

    for (int ch = 0; ch < 8; ch++) {
        if (ch < 7)
            proj_issue(sb + ((ch + 1) & 1) * P_STAGE, tid, woff, oc0, b, h, w0,
                       ch + 1, Bimg);
        CP_COMMIT();
        CP_WAIT(1);
        __syncthreads();

        const uint32_t st = sb + (ch & 1) * P_STAGE;
        const uint32_t uA = st + P_A, uB = st + P_B;

        #pragma unroll
        for (int s = 0; s < 2; s++) {
            uint32_t bh[4][4];
            #pragma unroll
            for (int np = 0; np < 4; np++) {
                const uint32_t bo = bLaneOff + (uint32_t)(s * 16 * 272 + np * 32);
                LDSM_X4_T(bh[np][0], bh[np][1], bh[np][2], bh[np][3], uB + bo);
            }
            #pragma unroll
            for (int mt = 0; mt < 2; mt++) {
                uint32_t ah[4];
                const uint32_t ao = aLaneOff + (uint32_t)(mt * 16 * 80 + s * 32);
                LDSM_X4(ah[0], ah[1], ah[2], ah[3], uA + ao);
                #pragma unroll
                for (int np = 0; np < 4; np++)
                    #pragma unroll
                    for (int half = 0; half < 2; half++)
                        mma_f16(acc[mt][np * 2 + half], ah,
                                bh[np][half * 2], bh[np][half * 2 + 1]);
            }
        }
        __syncthreads();
    }

    // ---- epilogue ----
    #pragma unroll
    for (int mt = 0; mt < 2; mt++) {
        const int mBase = warp_m * 32 + mt * 16 + (lane >> 2);
        #pragma unroll
        for (int oct = 0; oct < 8; oct++) {
            const int n = warp_n * 64 + oct * 8 + 2 * (lane & 3);
            const float* d = acc[mt][oct];
            #pragma unroll
            for (int rr = 0; rr < 2; rr++) {
                const int oc = oc0 + mBase + rr * 8;
                float v0 = d[rr * 2 + 0];
                float v1 = d[rr * 2 + 1];
                if (MODE == 2) {
                    const float bs = bias[oc];
                    const int w = w0 + n;
                    if (h < HH) {
                        if (w < WW)
                            Out[((size_t)(b * 256 + oc) * HH + h) * WW + w] = v0 + bs;
                        if (w + 1 < WW)
                            Out[((size_t)(b * 256 + oc) * HH + h) * WW + w + 1] = v1 + bs;
                    }
                } else {
                    if (MODE == 0) {
                        v0 *= 0.1767766952966369f;   // fold softmax scale into Q
                        v1 *= 0.1767766952966369f;
                    }
                    const int w  = w0 + n;
                    const int nw = (b * 32 + (h >> 3)) * 32 + (w >> 3);
                    const int l  = ((h & 7) << 3) | (w & 7);
                    const int cc = oc & 255;
                    const int idx2 = (((nw * 8 + (cc >> 5)) * 32 + (cc & 31)) * 64 + l) >> 1;
                    uint32_t* dst;
                    if (MODE == 0)           dst = reinterpret_cast<uint32_t*>(g_Q);
                    else if (oc0 < 256)      dst = reinterpret_cast<uint32_t*>(g_K);
                    else                     dst = reinterpret_cast<uint32_t*>(g_V);
                    dst[idx2] = pack_half(v0, v1);
                }
            }
        }
    }
}

// ---------------------------------------------------------------------------
// fp16 MMA attention: block = 128 threads = 2 window-heads, 2 warps per wh.
// ---------------------------------------------------------------------------
#define SLAB 4608                 // 32 rows * 144B
#define WHSZ (3 * SLAB)           // Q K V
#define ATT_SMEM (2 * WHSZ)       // 27648

__global__ __launch_bounds__(128)
void attn_mma()
{
    extern __shared__ char smem[];
    const int tid  = threadIdx.x;
    const int wid  = tid >> 5;
    const int lane = tid & 31;

    const __half* srcs[3] = {g_Q, g_K, g_V};
    #pragma unroll
    for (int sl = 0; sl < 2; sl++) {
        const size_t gbase = (size_t)(blockIdx.x * 2 + sl) * 2048;
        #pragma unroll
        for (int a = 0; a < 3; a++) {
            const uint4* src = reinterpret_cast<const uint4*>(srcs[a] + gbase);
            char* dstb = smem + sl * WHSZ + a * SLAB;
            #pragma unroll
            for (int i = 0; i < 2; i++) {
                const int idx = i * 128 + tid;           // 0..255 uint4
                const uint4 v = src[idx];
                *reinterpret_cast<uint4*>(dstb + (idx >> 3) * 144 + (idx & 7) * 16) = v;
            }
        }
    }
    __syncthreads();

    const uint32_t sb = smem_u32(smem) + (wid >> 1) * WHSZ;
    const uint32_t uQ = sb, uK = sb + SLAB, uV = sb + 2 * SLAB;
    const int whalf = wid & 1;
    const int wh = blockIdx.x * 2 + (wid >> 1);

    const int g = lane >> 2;
    const int t = lane & 3;

    const int n    = wh >> 3;
    const int head = wh & 7;
    const int b    = n >> 10;
    const int hw   = (n >> 5) & 31;
    const int wwin = n & 31;

    const uint32_t qRow = (uint32_t)((lane & 7) + ((lane >> 4) & 1) * 8);
    const uint32_t qCol = (uint32_t)(((lane >> 3) & 1) * 16);
    const uint32_t kRow = (uint32_t)((lane & 7) + ((lane >> 3) & 1) * 8);
    const uint32_t kCol = (uint32_t)((lane >> 4) * 16);
    const uint32_t vRow = (uint32_t)((lane & 7) + ((lane >> 4) & 1) * 8);
    const uint32_t vCol = (uint32_t)(((lane >> 3) & 1) * 16);

    #pragma unroll
    for (int mt = 0; mt < 2; mt++) {
        const int ltile = whalf * 2 + mt;

        float s[8][4];
        #pragma unroll
        for (int j = 0; j < 8; j++)
            #pragma unroll
            for (int k = 0; k < 4; k++) s[j][k] = 0.f;

        #pragma unroll
        for (int kt = 0; kt < 2; kt++) {
            uint32_t ah[4];
            const uint32_t ao = (qRow + kt * 16) * 144 + qCol + (uint32_t)(ltile * 32);
            LDSM_X4_T(ah[0], ah[1], ah[2], ah[3], uQ + ao);
            #pragma unroll
            for (int nt = 0; nt < 4; nt++) {
                uint32_t bh[4];
                const uint32_t bo = (kRow + kt * 16) * 144 + kCol + (uint32_t)(nt * 32);
                LDSM_X4_T(bh[0], bh[1], bh[2], bh[3], uK + bo);
                #pragma unroll
                for (int half = 0; half < 2; half++)
                    mma_f16(s[nt * 2 + half], ah, bh[half * 2], bh[half * 2 + 1]);
            }
        }

        float mx0 = -1e30f, mx1 = -1e30f;
        #pragma unroll
        for (int j = 0; j < 8; j++) {
            mx0 = fmaxf(mx0, fmaxf(s[j][0], s[j][1]));
            mx1 = fmaxf(mx1, fmaxf(s[j][2], s[j][3]));
        }
        mx0 = fmaxf(mx0, __shfl_xor_sync(0xffffffffu, mx0, 1));
        mx0 = fmaxf(mx0, __shfl_xor_sync(0xffffffffu, mx0, 2));
        mx1 = fmaxf(mx1, __shfl_xor_sync(0xffffffffu, mx1, 1));
        mx1 = fmaxf(mx1, __shfl_xor_sync(0xffffffffu, mx1, 2));

        float sum0 = 0.f, sum1 = 0.f;
        uint32_t ph01[8], ph23[8];
        #pragma unroll
        for (int j = 0; j < 8; j++) {
            const float e0 = __expf(s[j][0] - mx0);
            const float e1 = __expf(s[j][1] - mx0);
            const float e2 = __expf(s[j][2] - mx1);
            const float e3 = __expf(s[j][3] - mx1);
            sum0 += e0 + e1;
            sum1 += e2 + e3;
            ph01[j] = pack_half(e0, e1);
            ph23[j] = pack_half(e2, e3);
        }
        sum0 += __shfl_xor_sync(0xffffffffu, sum0, 1);
        sum0 += __shfl_xor_sync(0xffffffffu, sum0, 2);
        sum1 += __shfl_xor_sync(0xffffffffu, sum1, 1);
        sum1 += __shfl_xor_sync(0xffffffffu, sum1, 2);
        const float inv0 = 1.f / sum0;
        const float inv1 = 1.f / sum1;

        float o[4][4];
        #pragma unroll
        for (int j = 0; j < 4; j++)
            #pragma unroll
            for (int k = 0; k < 4; k++) o[j][k] = 0.f;

        #pragma unroll
        for (int kt = 0; kt < 4; kt++) {
            uint32_t ap[4];
            ap[0] = ph01[2 * kt];     ap[1] = ph23[2 * kt];
            ap[2] = ph01[2 * kt + 1]; ap[3] = ph23[2 * kt + 1];
            #pragma unroll
            for (int dt2 = 0; dt2 < 2; dt2++) {
                uint32_t bh[4];
                const uint32_t bo = (vRow + dt2 * 16) * 144 + vCol + (uint32_t)(kt * 32);
                LDSM_X4(bh[0], bh[1], bh[2], bh[3], uV + bo);
                #pragma unroll
                for (int half = 0; half < 2; half++)
                    mma_f16(o[dt2 * 2 + half], ap, bh[half * 2], bh[half * 2 + 1]);
            }
        }

        // ---- store fp16 to padded image ----
        const int l0 = ltile * 16 + g;
        const int l1 = l0 + 8;
        const int h0 = hw * 8 + (l0 >> 3), w0p = wwin * 8 + (l0 & 7);
        const int h1 = hw * 8 + (l1 >> 3), w1p = wwin * 8 + (l1 & 7);
        #pragma unroll
        for (int dt = 0; dt < 4; dt++) {
            const int c = head * 32 + dt * 8 + 2 * t;
            g_A[((b * 256 + c) << 16)     + (h0 << 8) + w0p] = __float2half_rn(o[dt][0] * inv0);
            g_A[((b * 256 + c + 1) << 16) + (h0 << 8) + w0p] = __float2half_rn(o[dt][1] * inv0);
            g_A[((b * 256 + c) << 16)     + (h1 << 8) + w1p] = __float2half_rn(o[dt][2] * inv1);
            g_A[((b * 256 + c + 1) << 16) + (h1 << 8) + w1p] = __float2half_rn(o[dt][3] * inv1);
        }
    }
}

// ---------------------------------------------------------------------------
extern "C" void kernel_launch(void* const* d_in, const int* in_sizes, int n_in,
                              void* d_out, int out_size)
{
    const float* x_q    = (const float*)d_in[0];
    const float* x_kv   = (const float*)d_in[1];
    const float* w_q    = (const float*)d_in[2];
    const float* w_kv   = (const float*)d_in[3];
    const float* w_proj = (const float*)d_in[4];
    const float* b_proj = (const float*)d_in[5];
    float* out = (float*)d_out;

    cudaFuncSetAttribute(attn_mma, cudaFuncAttributeMaxDynamicSharedMemorySize, ATT_SMEM);
    cudaFuncSetAttribute(proj_v2<0>, cudaFuncAttributeMaxDynamicSharedMemorySize, P_SMEM);
    cudaFuncSetAttribute(proj_v2<1>, cudaFuncAttributeMaxDynamicSharedMemorySize, P_SMEM);
    cudaFuncSetAttribute(proj_v2<2>, cudaFuncAttributeMaxDynamicSharedMemorySize, P_SMEM);

    __half *xq, *xk, *ai;
    cudaGetSymbolAddress((void**)&xq, g_Xq);
    cudaGetSymbolAddress((void**)&xk, g_Xk);
    cudaGetSymbolAddress((void**)&ai, g_A);

    prep_w<<<1024, 256>>>(w_q, w_kv, w_proj);
    prep_x<<<131072, 256>>>(x_q, x_kv);

    const int pixTiles = (BB * HP * WP) / 128;   // 2048
    proj_v2<0><<<dim3(pixTiles, 2), 256, P_SMEM>>>(xq, 0,      nullptr, nullptr);
    proj_v2<1><<<dim3(pixTiles, 4), 256, P_SMEM>>>(xk, 65536,  nullptr, nullptr);
    attn_mma<<<16384, 128, ATT_SMEM>>>();
    proj_v2<2><<<dim3(pixTiles, 2), 256, P_SMEM>>>(ai, 196608, b_proj, out);
}